// round 12
// baseline (speedup 1.0000x reference)
#include <cuda_runtime.h>
#include <cuda_fp16.h>
#include <math.h>
#include <stdint.h>

// ---------------- problem constants ----------------
#define BB 16
#define TT 256
#define DD 512
#define LL1 51
#define MM (BB*TT)            // 4096
#define LL2 (LL1*LL1)         // 2601
#define NCHAINS (BB*LL2)      // 41616
#define KP 512                // plain fp16 GEMM
#define KC 64
#define NCH (KP/KC)           // 8
#define LOG2PI 1.8378770664093453f
#define LN2F 0.6931471805599453f

// B' column space (same as R11):
#define NP_CH  2688
#define PS_W   0
#define PS_MU  128
#define PS_VAR 256
#define PT_W   384
#define PT_MU0 (PT_W  + NP_CH)   // 3072
#define PT_MU1 (PT_MU0 + NP_CH)  // 5760
#define PT_D0  (PT_MU1 + NP_CH)  // 8448
#define PT_SUM (PT_D0 + NP_CH)   // 11136
#define PT_D1  (PT_SUM + NP_CH)  // 13824
#define NTOT   (PT_D1 + NP_CH)   // 16512
#define NTILES 129
// fp32 buffer: cols [0, 3072) = s-planes + tw
#define C32W   3072
// fp16 buffer: cols [3072, 16512) -> local offsets (halves)
#define C16W   13440
#define H_M0   0
#define H_M1   2688
#define H_D0   5376
#define H_SV   8064
#define H_D1   10752

// ---------------- scratch (device globals) ----------------
__device__ __align__(256) __half g_Ap[(size_t)MM*KP];
__device__ __align__(256) __half g_Bp[(size_t)NTOT*KP];
__device__ __align__(256) float g_bias[NTOT];
__device__ __align__(256) float  g_C [(size_t)MM*C32W];
__device__ __align__(256) __half g_Ct[(size_t)MM*C16W];

// ---------------- PTX helpers ----------------
__device__ __forceinline__ uint32_t smem_u32(const void* p) {
    uint32_t a;
    asm("{ .reg .u64 t; cvta.to.shared.u64 t, %1; cvt.u32.u64 %0, t; }" : "=r"(a) : "l"(p));
    return a;
}
__device__ __forceinline__ void cp_async16(uint32_t dst, const void* src) {
    asm volatile("cp.async.cg.shared.global [%0], [%1], 16;" :: "r"(dst), "l"(src));
}
#define CP_COMMIT() asm volatile("cp.async.commit_group;" ::: "memory")
#define CP_WAIT(n)  asm volatile("cp.async.wait_group %0;" :: "n"(n) : "memory")

__device__ __forceinline__ void ldmx4(uint32_t* r, uint32_t addr) {
    asm volatile("ldmatrix.sync.aligned.m8n8.x4.shared.b16 {%0,%1,%2,%3}, [%4];"
        : "=r"(r[0]), "=r"(r[1]), "=r"(r[2]), "=r"(r[3]) : "r"(addr));
}
__device__ __forceinline__ void mma16816(float* c, const uint32_t* a, uint32_t b0, uint32_t b1) {
    asm volatile("mma.sync.aligned.m16n8k16.row.col.f32.f16.f16.f32 "
        "{%0,%1,%2,%3}, {%4,%5,%6,%7}, {%8,%9}, {%0,%1,%2,%3};"
        : "+f"(c[0]), "+f"(c[1]), "+f"(c[2]), "+f"(c[3])
        : "r"(a[0]), "r"(a[1]), "r"(a[2]), "r"(a[3]), "r"(b0), "r"(b1));
}

// ---------------- fused prep: 9 W jobs + x-convert + bias (unchanged) -------
__global__ void prep_all(const float* __restrict__ x,
    const float* __restrict__ Ws_w, const float* __restrict__ Ws_mu, const float* __restrict__ Ws_var,
    const float* __restrict__ Wt_w, const float* __restrict__ Wt_mu, const float* __restrict__ Wt_var,
    const float* __restrict__ bsw, const float* __restrict__ bsmu, const float* __restrict__ bsvar,
    const float* __restrict__ btw, const float* __restrict__ btmu, const float* __restrict__ btvar)
{
    int z = blockIdx.z;
    int tx = threadIdx.x, ty = threadIdx.y;
    int tid = ty * 32 + tx;

    if (z == 9) {
        int linb = blockIdx.y * gridDim.x + blockIdx.x;
        int nth  = gridDim.x * gridDim.y * 256;
        int gtid = linb * 256 + tid;
        for (int t = gtid; t < MM * DD; t += nth)
            g_Ap[t] = __float2half(x[t]);
        for (int c = gtid; c < NTOT; c += nth) {
            float v = 0.f;
            if (c < PS_MU)        { if (c < LL1) v = bsw[c]; }
            else if (c < PS_VAR)  { int n = c - PS_MU;  if (n < LL1) v = bsmu[n]; }
            else if (c < PT_W)    { int n = c - PS_VAR; if (n < LL1) v = bsvar[n]; }
            else if (c < PT_MU0)  { int n = c - PT_W;   if (n < LL2) v = btw[n]; }
            else if (c < PT_MU1)  { int n = c - PT_MU0; if (n < LL2) v = btmu[2 * n]; }
            else if (c < PT_D0)   { int n = c - PT_MU1; if (n < LL2) v = btmu[2 * n + 1]; }
            else if (c < PT_SUM)  { int n = c - PT_D0;  if (n < LL2) v = btvar[4 * n]; }
            else if (c < PT_D1)   { int n = c - PT_SUM; if (n < LL2) v = btvar[4 * n + 1] + btvar[4 * n + 2]; }
            else                  { int n = c - PT_D1;  if (n < LL2) v = btvar[4 * n + 3]; }
            g_bias[c] = v;
        }
        return;
    }

    const float* W; int srcN, dstOff, nValid, colMul, colAdd, colAdd2, bx;
    switch (z) {
        case 0: W = Ws_w;   srcN = LL1;     dstOff = PS_W;   nValid = LL1; colMul = 1; colAdd = 0; colAdd2 = -1; bx = 4;  break;
        case 1: W = Ws_mu;  srcN = LL1;     dstOff = PS_MU;  nValid = LL1; colMul = 1; colAdd = 0; colAdd2 = -1; bx = 4;  break;
        case 2: W = Ws_var; srcN = LL1;     dstOff = PS_VAR; nValid = LL1; colMul = 1; colAdd = 0; colAdd2 = -1; bx = 4;  break;
        case 3: W = Wt_w;   srcN = LL2;     dstOff = PT_W;   nValid = LL2; colMul = 1; colAdd = 0; colAdd2 = -1; bx = 84; break;
        case 4: W = Wt_mu;  srcN = LL2 * 2; dstOff = PT_MU0; nValid = LL2; colMul = 2; colAdd = 0; colAdd2 = -1; bx = 84; break;
        case 5: W = Wt_mu;  srcN = LL2 * 2; dstOff = PT_MU1; nValid = LL2; colMul = 2; colAdd = 1; colAdd2 = -1; bx = 84; break;
        case 6: W = Wt_var; srcN = LL2 * 4; dstOff = PT_D0;  nValid = LL2; colMul = 4; colAdd = 0; colAdd2 = -1; bx = 84; break;
        case 7: W = Wt_var; srcN = LL2 * 4; dstOff = PT_SUM; nValid = LL2; colMul = 4; colAdd = 1; colAdd2 = 2;  bx = 84; break;
        default:W = Wt_var; srcN = LL2 * 4; dstOff = PT_D1;  nValid = LL2; colMul = 4; colAdd = 3; colAdd2 = -1; bx = 84; break;
    }
    if ((int)blockIdx.x >= bx) return;

    __shared__ float tile[32][33];
    int n = blockIdx.x * 32 + tx;
    #pragma unroll
    for (int i = 0; i < 4; i++) {
        int k = blockIdx.y * 32 + ty + i * 8;
        float v = 0.f;
        if (n < nValid) {
            v = W[(size_t)k * srcN + n * colMul + colAdd];
            if (colAdd2 >= 0) v += W[(size_t)k * srcN + n * colMul + colAdd2];
        }
        tile[ty + i * 8][tx] = v;
    }
    __syncthreads();
    #pragma unroll
    for (int i = 0; i < 4; i++) {
        int n2 = blockIdx.x * 32 + ty + i * 8;
        int k2 = blockIdx.y * 32 + tx;
        g_Bp[(size_t)(dstOff + n2) * KP + k2] = __float2half(tile[tx][ty + i * 8]);
    }
}

// ---------------- HMMA GEMM: 128x128 CTA, 256 threads, KC=64, 3-stage ------
#define TILE_STRIDE 72
#define HALF_BYTES 18432
#define BUF_BYTES 36864
#define SMEM_BYTES (3*BUF_BYTES)
#define STG_STRIDE 132

__device__ __forceinline__ void issue_tile(uint32_t dstBase,
                                           const __half* __restrict__ src,
                                           int row0, int kc, int tid) {
    #pragma unroll
    for (int i = 0; i < 4; i++) {
        int ci  = i * 256 + tid;
        int r   = ci >> 3;
        int c16 = ci & 7;
        uint32_t dst = dstBase + (uint32_t)(r * (TILE_STRIDE * 2) + c16 * 16);
        cp_async16(dst, src + (size_t)(row0 + r) * KP + kc + c16 * 8);
    }
}

__device__ __forceinline__ float expclip(float v) {
    return __expf(fminf(fmaxf(v, -1.f), 1.f));
}
__device__ __forceinline__ float tanh09(float v) {
    float xc = fminf(fmaxf(0.5f * v, -15.f), 15.f);
    float e = __expf(2.f * xc);
    return 0.9f * __fdividef(e - 1.f, e + 1.f);
}

__global__ void __launch_bounds__(256, 2) gemm_tc()
{
    extern __shared__ char smem[];
    uint32_t sbase = smem_u32(smem);
    int tid = threadIdx.x, wid = tid >> 5, lane = tid & 31;
    int m0 = blockIdx.x * 128;
    int n0 = blockIdx.y * 128;

    int wm = (wid & 3) * 32;
    int wn = (wid >> 2) * 64;
    int lr = lane & 15;
    int lc = (lane >> 4) * 8;

    float acc[2][8][4];
    #pragma unroll
    for (int mi = 0; mi < 2; mi++)
        #pragma unroll
        for (int ni = 0; ni < 8; ni++)
            #pragma unroll
            for (int q = 0; q < 4; q++) acc[mi][ni][q] = 0.f;

    issue_tile(sbase,              g_Ap, m0, 0, tid);
    issue_tile(sbase + HALF_BYTES, g_Bp, n0, 0, tid);
    CP_COMMIT();
    issue_tile(sbase + BUF_BYTES,              g_Ap, m0, KC, tid);
    issue_tile(sbase + BUF_BYTES + HALF_BYTES, g_Bp, n0, KC, tid);
    CP_COMMIT();

    for (int c = 0; c < NCH; c++) {
        if (c + 1 < NCH) { CP_WAIT(1); } else { CP_WAIT(0); }
        __syncthreads();
        if (c + 2 < NCH) {
            uint32_t nb = sbase + (uint32_t)(((c + 2) % 3) * BUF_BYTES);
            issue_tile(nb,              g_Ap, m0, (c + 2) * KC, tid);
            issue_tile(nb + HALF_BYTES, g_Bp, n0, (c + 2) * KC, tid);
            CP_COMMIT();
        }
        uint32_t aBase = sbase + (uint32_t)((c % 3) * BUF_BYTES);
        uint32_t bBase = aBase + HALF_BYTES;
        #pragma unroll
        for (int ks = 0; ks < 4; ks++) {
            uint32_t af[2][4];
            #pragma unroll
            for (int mi = 0; mi < 2; mi++)
                ldmx4(af[mi], aBase + (uint32_t)(((wm + mi * 16 + lr) * TILE_STRIDE
                                                  + ks * 16 + lc) * 2));
            uint32_t bf[4][4];
            #pragma unroll
            for (int nb = 0; nb < 4; nb++)
                ldmx4(bf[nb], bBase + (uint32_t)(((wn + nb * 16 + lr) * TILE_STRIDE
                                                  + ks * 16 + lc) * 2));
            #pragma unroll
            for (int mi = 0; mi < 2; mi++)
                #pragma unroll
                for (int nb = 0; nb < 4; nb++) {
                    mma16816(acc[mi][nb * 2 + 0], af[mi], bf[nb][0], bf[nb][2]);
                    mma16816(acc[mi][nb * 2 + 1], af[mi], bf[nb][1], bf[nb][3]);
                }
        }
    }
    __syncthreads();

    float* stage = (float*)smem;
    int gr = lane >> 2;
    int gc = (lane & 3) * 2;
    #pragma unroll
    for (int mi = 0; mi < 2; mi++)
        #pragma unroll
        for (int ni = 0; ni < 8; ni++) {
            int row = wm + mi * 16 + gr;
            int col = wn + ni * 8 + gc;
            *(float2*)&stage[row * STG_STRIDE + col] =
                make_float2(acc[mi][ni][0], acc[mi][ni][1]);
            *(float2*)&stage[(row + 8) * STG_STRIDE + col] =
                make_float2(acc[mi][ni][2], acc[mi][ni][3]);
        }
    __syncthreads();

    // mode: 1 = exp(clip) [s_var, d0, d1 planes], 2 = 0.9*tanh(0.5x) [sum plane]
    int mode = 0;
    if (n0 == PS_VAR || (n0 >= PT_D0 && n0 < PT_SUM) || n0 >= PT_D1) mode = 1;
    else if (n0 >= PT_SUM && n0 < PT_D1) mode = 2;

    for (int i = tid; i < 128 * 32; i += 256) {
        int row = i >> 5, q = i & 31;
        int col = q * 4;
        float4 b4 = *(const float4*)&g_bias[n0 + col];
        const float* s = &stage[row * STG_STRIDE + col];
        float4 v = make_float4(s[0] + b4.x, s[1] + b4.y, s[2] + b4.z, s[3] + b4.w);
        if (mode == 1) {
            v.x = expclip(v.x); v.y = expclip(v.y); v.z = expclip(v.z); v.w = expclip(v.w);
        } else if (mode == 2) {
            v.x = tanh09(v.x); v.y = tanh09(v.y); v.z = tanh09(v.z); v.w = tanh09(v.w);
        }
        if (n0 < C32W) {
            *(float4*)&g_C[(size_t)(m0 + row) * C32W + n0 + col] = v;
        } else {
            __half2 h0 = __floats2half2_rn(v.x, v.y);
            __half2 h1 = __floats2half2_rn(v.z, v.w);
            uint2 pk;
            pk.x = *(uint32_t*)&h0;
            pk.y = *(uint32_t*)&h1;
            *(uint2*)(g_Ct + (size_t)(m0 + row) * C16W + (n0 - C32W) + col) = pk;
        }
    }
}

// ---------------- scan ----------------
struct Step { float sw, smu, svar, tw, m0, m1, d0, sv, d1; };

__device__ __forceinline__ Step load_step(int row, int chain, int j) {
    const float*  b32 = g_C  + (size_t)row * C32W;
    const __half* b16 = g_Ct + (size_t)row * C16W;
    Step s;
    // s-planes: heavily reused across chains -> keep caching
    s.sw   = __ldg(b32 + PS_W   + j);
    s.smu  = __ldg(b32 + PS_MU  + j);
    s.svar = __ldg(b32 + PS_VAR + j);
    // streamed planes: evict-first
    s.tw   = __ldcs(b32 + PT_W + chain);
    s.m0   = __half2float(__ldcs(b16 + H_M0 + chain));
    s.m1   = __half2float(__ldcs(b16 + H_M1 + chain));
    s.d0   = __half2float(__ldcs(b16 + H_D0 + chain));
    s.sv   = __half2float(__ldcs(b16 + H_SV + chain));
    s.d1   = __half2float(__ldcs(b16 + H_D1 + chain));
    return s;
}

// generic merge (t=0 prologue only)
__device__ __forceinline__ void merge2x2(
    float tmu0, float tmu1, float tv00, float tv01, float tv11,
    float nmu, float nvar, bool child,
    float& zeta, float& mu_new, float& var_new)
{
    float det  = tv00 * tv11 - tv01 * tv01;
    float idet = __fdividef(1.f, det);
    float a  = tv11 * idet;
    float bo = -tv01 * idet;
    float dd = tv00 * idet;
    float e0 = a  * tmu0 + bo * tmu1;
    float e1 = bo * tmu0 + dd * tmu1;
    float quad1 = e0 * e0 * tv00 + 2.f * e0 * e1 * tv01 + e1 * e1 * tv11;
    float l2   = __fdividef(1.f, nvar);
    float eta2 = nmu * l2;
    float den, keep, es, la, iden;
    if (child) { den = dd + l2; iden = __fdividef(1.f, den); keep = e0; es = e1 + eta2; la = a  - bo * bo * iden; }
    else       { den = a  + l2; iden = __fdividef(1.f, den); keep = e1; es = e0 + eta2; la = dd - bo * bo * iden; }
    float eta = keep - bo * iden * es;
    var_new = __fdividef(1.f, la);
    mu_new  = var_new * eta;
    float logp = __logf(det * nvar * den * la);
    zeta = -0.5f * (LOG2PI + logp + quad1 + nmu * nmu * l2
                    - es * es * iden - eta * eta * var_new);
}

// one scan step (short-critical-path form)
__device__ __forceinline__ float scan_step(const Step& cur, float& mu_p, float& var_p)
{
    // off-path precompute
    float w01  = cur.sv * sqrtf(cur.d0 * cur.d1);
    float det  = cur.d0 * cur.d1 - w01 * w01;
    float idet = __frcp_rn(det);
    float a  = cur.d1 * idet;
    float bo = -w01 * idet;
    float dd = cur.d0 * idet;
    float e0 = a  * cur.m0 + bo * cur.m1;
    float e1 = bo * cur.m0 + dd * cur.m1;
    float quad1 = e0 * e0 * cur.d0 + 2.f * e0 * e1 * w01 + e1 * e1 * cur.d1;
    float bo2 = bo * bo;

    // recurrence critical path
    float vsum = var_p + cur.svar;
    float lg   = __log2f(vsum);
    float logv = lg * LN2F;
    float inv  = __frcp_rn(vsum);
    float nvar = fmaf(lg, -0.5f * LN2F, vsum);
    float nmu  = (mu_p * cur.svar + cur.smu * var_p) * inv;
    float diff = mu_p - cur.smu;
    float scale_c = -0.5f * (LOG2PI + logv + diff * diff * inv);

    float h    = fmaf(a, nvar, 1.f);
    float bo2n = bo2 * nvar;
    float p    = fmaf(dd, h, -bo2n);
    float rp   = __frcp_rn(p);
    float esn  = fmaf(e0, nvar, nmu);
    float etah = fmaf(e1, h, -bo * esn);
    float var_n = h * rp;
    float mu_n  = etah * rp;

    // zeta (off-path)
    float invn = __frcp_rn(nvar);
    float invh = __frcp_rn(h);
    float logdp = __log2f(det * p) * LN2F;
    float zeta = -0.5f * (LOG2PI + logdp + quad1
                          + nmu * nmu * invn
                          - esn * esn * invn * invh
                          - etah * etah * invh * rp);

    mu_p = mu_n; var_p = var_n;
    return scale_c + zeta + cur.tw + cur.sw;
}

#define RING 6

// single-wave: ceil(41616/288)=145 CTAs x 288 threads
__global__ __launch_bounds__(288) void scan_kernel(float* __restrict__ out)
{
    int q = blockIdx.x * 288 + threadIdx.x;
    if (q >= NCHAINS) return;
    int b = q / LL2;
    int chain = q - b * LL2;
    int j = chain % LL1;
    int row0 = b * TT;

    Step buf[RING];
    Step s0 = load_step(row0, chain, j);
    #pragma unroll
    for (int k = 0; k < RING; k++)
        buf[k] = load_step(row0 + 1 + k, chain, j);

    // ---- t = 0 prologue ----
    float v01 = s0.sv * sqrtf(s0.d0 * s0.d1);
    float sc0, mu_c, var_c;
    merge2x2(s0.m0, s0.m1, s0.d0, v01, s0.d1, s0.smu, s0.svar, true, sc0, mu_c, var_c);

    Step s1 = buf[0];
    float u01 = s1.sv * sqrtf(s1.d0 * s1.d1);
    float sp0, mu_p, var_p;
    merge2x2(s1.m0, s1.m1, s1.d0, u01, s1.d1, mu_c, var_c, false, sp0, mu_p, var_p);

    out[(size_t)row0 * LL2 + chain] = sc0 + sp0 + s0.tw + s0.sw;

    // ---- t = 1..252 in 42 blocks of 6 (static ring slots) ----
    float* optr = out + (size_t)row0 * LL2 + chain;
    for (int blk = 0; blk < 42; blk++) {
        int tbase = blk * RING + 1;
        #pragma unroll
        for (int u = 0; u < RING; u++) {
            int t = tbase + u;
            Step cur = buf[u];
            if (t + RING < TT)
                buf[u] = load_step(row0 + t + RING, chain, j);
            float r = scan_step(cur, mu_p, var_p);
            optr[(size_t)t * LL2] = r;
        }
    }
    // ---- tail t = 253, 254, 255 ----
    #pragma unroll
    for (int u = 0; u < 3; u++) {
        int t = 253 + u;
        float r = scan_step(buf[u], mu_p, var_p);
        optr[(size_t)t * LL2] = r;
    }
}

// ---------------- launch ----------------
extern "C" void kernel_launch(void* const* d_in, const int* in_sizes, int n_in,
                              void* d_out, int out_size)
{
    const float* x      = (const float*)d_in[0];
    const float* Ws_w   = (const float*)d_in[1];
    const float* bs_w   = (const float*)d_in[2];
    const float* Ws_mu  = (const float*)d_in[3];
    const float* bs_mu  = (const float*)d_in[4];
    const float* Ws_var = (const float*)d_in[5];
    const float* bs_var = (const float*)d_in[6];
    const float* Wt_w   = (const float*)d_in[7];
    const float* bt_w   = (const float*)d_in[8];
    const float* Wt_mu  = (const float*)d_in[9];
    const float* bt_mu  = (const float*)d_in[10];
    const float* Wt_var = (const float*)d_in[11];
    const float* bt_var = (const float*)d_in[12];
    float* out = (float*)d_out;

    cudaFuncSetAttribute(gemm_tc, cudaFuncAttributeMaxDynamicSharedMemorySize, SMEM_BYTES);

    prep_all<<<dim3(84, 16, 10), dim3(32, 8)>>>(x, Ws_w, Ws_mu, Ws_var, Wt_w, Wt_mu, Wt_var,
                                                bs_w, bs_mu, bs_var, bt_w, bt_mu, bt_var);

    gemm_tc<<<dim3(32, NTILES), 256, SMEM_BYTES>>>();

    scan_kernel<<<(NCHAINS + 287) / 288, 288>>>(out);
}

// round 13
// speedup vs baseline: 1.2607x; 1.2607x over previous
#include <cuda_runtime.h>
#include <cuda_fp16.h>
#include <math.h>
#include <stdint.h>

// ---------------- problem constants ----------------
#define BB 16
#define TT 256
#define DD 512
#define LL1 51
#define MM (BB*TT)            // 4096
#define LL2 (LL1*LL1)         // 2601
#define NCHAINS (BB*LL2)      // 41616
#define KP 512                // plain fp16 GEMM
#define KC 64
#define NCH (KP/KC)           // 8
#define LOG2PI 1.8378770664093453f
#define LN2F 0.6931471805599453f

// planar output layout (offsets multiples of 128)
#define NP_CH  2688
#define PS_W   0
#define PS_MU  128
#define PS_VAR 256
#define PT_W   384
#define PT_MU0 (PT_W  + NP_CH)   // 3072
#define PT_MU1 (PT_MU0 + NP_CH)  // 5760
#define PT_D0  (PT_MU1 + NP_CH)  // 8448
#define PT_SUM (PT_D0 + NP_CH)   // 11136
#define PT_D1  (PT_SUM + NP_CH)  // 13824
#define NTOT   (PT_D1 + NP_CH)   // 16512
#define NTILES 129               // 128-wide tiles

// ---------------- scratch (device globals) ----------------
__device__ __align__(256) __half g_Ap[(size_t)MM*KP];
__device__ __align__(256) __half g_Bp[(size_t)NTOT*KP];
__device__ __align__(256) float g_bias[NTOT];
__device__ __align__(256) float g_C[(size_t)MM*NTOT];

// ---------------- PTX helpers ----------------
__device__ __forceinline__ uint32_t smem_u32(const void* p) {
    uint32_t a;
    asm("{ .reg .u64 t; cvta.to.shared.u64 t, %1; cvt.u32.u64 %0, t; }" : "=r"(a) : "l"(p));
    return a;
}
__device__ __forceinline__ void cp_async16(uint32_t dst, const void* src) {
    asm volatile("cp.async.cg.shared.global [%0], [%1], 16;" :: "r"(dst), "l"(src));
}
#define CP_COMMIT() asm volatile("cp.async.commit_group;" ::: "memory")
#define CP_WAIT(n)  asm volatile("cp.async.wait_group %0;" :: "n"(n) : "memory")

__device__ __forceinline__ void ldmx4(uint32_t* r, uint32_t addr) {
    asm volatile("ldmatrix.sync.aligned.m8n8.x4.shared.b16 {%0,%1,%2,%3}, [%4];"
        : "=r"(r[0]), "=r"(r[1]), "=r"(r[2]), "=r"(r[3]) : "r"(addr));
}
__device__ __forceinline__ void mma16816(float* c, const uint32_t* a, uint32_t b0, uint32_t b1) {
    asm volatile("mma.sync.aligned.m16n8k16.row.col.f32.f16.f16.f32 "
        "{%0,%1,%2,%3}, {%4,%5,%6,%7}, {%8,%9}, {%0,%1,%2,%3};"
        : "+f"(c[0]), "+f"(c[1]), "+f"(c[2]), "+f"(c[3])
        : "r"(a[0]), "r"(a[1]), "r"(a[2]), "r"(a[3]), "r"(b0), "r"(b1));
}

// ---------------- fused prep: 8 W jobs + x-convert + bias ----------------
// z: 0 = tw (+ s_w fold), 1 = s_mu, 2 = s_var, 3 = mu0, 4 = mu1,
//    5 = d0, 6 = sum, 7 = d1, 8 = x + bias
__global__ void prep_all(const float* __restrict__ x,
    const float* __restrict__ Ws_w, const float* __restrict__ Ws_mu, const float* __restrict__ Ws_var,
    const float* __restrict__ Wt_w, const float* __restrict__ Wt_mu, const float* __restrict__ Wt_var,
    const float* __restrict__ bsw, const float* __restrict__ bsmu, const float* __restrict__ bsvar,
    const float* __restrict__ btw, const float* __restrict__ btmu, const float* __restrict__ btvar)
{
    int z = blockIdx.z;
    int tx = threadIdx.x, ty = threadIdx.y;
    int tid = ty * 32 + tx;

    if (z == 8) {
        int linb = blockIdx.y * gridDim.x + blockIdx.x;
        int nth  = gridDim.x * gridDim.y * 256;
        int gtid = linb * 256 + tid;
        for (int t = gtid; t < MM * DD; t += nth)
            g_Ap[t] = __float2half(x[t]);
        for (int c = gtid; c < NTOT; c += nth) {
            float v = 0.f;
            if (c < PS_MU)        { /* s_w plane unused */ }
            else if (c < PS_VAR)  { int n = c - PS_MU;  if (n < LL1) v = bsmu[n]; }
            else if (c < PT_W)    { int n = c - PS_VAR; if (n < LL1) v = bsvar[n]; }
            else if (c < PT_MU0)  { int n = c - PT_W;   if (n < LL2) v = btw[n] + bsw[n % LL1]; }
            else if (c < PT_MU1)  { int n = c - PT_MU0; if (n < LL2) v = btmu[2 * n]; }
            else if (c < PT_D0)   { int n = c - PT_MU1; if (n < LL2) v = btmu[2 * n + 1]; }
            else if (c < PT_SUM)  { int n = c - PT_D0;  if (n < LL2) v = btvar[4 * n]; }
            else if (c < PT_D1)   { int n = c - PT_SUM; if (n < LL2) v = btvar[4 * n + 1] + btvar[4 * n + 2]; }
            else                  { int n = c - PT_D1;  if (n < LL2) v = btvar[4 * n + 3]; }
            g_bias[c] = v;
        }
        return;
    }

    int dstOff, nValid, bx;
    switch (z) {
        case 0: dstOff = PT_W;   nValid = LL2; bx = 84; break;
        case 1: dstOff = PS_MU;  nValid = LL1; bx = 4;  break;
        case 2: dstOff = PS_VAR; nValid = LL1; bx = 4;  break;
        case 3: dstOff = PT_MU0; nValid = LL2; bx = 84; break;
        case 4: dstOff = PT_MU1; nValid = LL2; bx = 84; break;
        case 5: dstOff = PT_D0;  nValid = LL2; bx = 84; break;
        case 6: dstOff = PT_SUM; nValid = LL2; bx = 84; break;
        default:dstOff = PT_D1;  nValid = LL2; bx = 84; break;
    }
    if ((int)blockIdx.x >= bx) return;

    __shared__ float tile[32][33];
    int n = blockIdx.x * 32 + tx;
    #pragma unroll
    for (int i = 0; i < 4; i++) {
        int k = blockIdx.y * 32 + ty + i * 8;
        float v = 0.f;
        if (n < nValid) {
            switch (z) {
                case 0: v = Wt_w[(size_t)k * LL2 + n] + Ws_w[(size_t)k * LL1 + n % LL1]; break;
                case 1: v = Ws_mu[(size_t)k * LL1 + n]; break;
                case 2: v = Ws_var[(size_t)k * LL1 + n]; break;
                case 3: v = Wt_mu[(size_t)k * (LL2 * 2) + 2 * n]; break;
                case 4: v = Wt_mu[(size_t)k * (LL2 * 2) + 2 * n + 1]; break;
                case 5: v = Wt_var[(size_t)k * (LL2 * 4) + 4 * n]; break;
                case 6: v = Wt_var[(size_t)k * (LL2 * 4) + 4 * n + 1]
                          + Wt_var[(size_t)k * (LL2 * 4) + 4 * n + 2]; break;
                default:v = Wt_var[(size_t)k * (LL2 * 4) + 4 * n + 3]; break;
            }
        }
        tile[ty + i * 8][tx] = v;
    }
    __syncthreads();
    #pragma unroll
    for (int i = 0; i < 4; i++) {
        int n2 = blockIdx.x * 32 + ty + i * 8;
        int k2 = blockIdx.y * 32 + tx;
        g_Bp[(size_t)(dstOff + n2) * KP + k2] = __float2half(tile[tx][ty + i * 8]);
    }
}

// ---------------- HMMA GEMM: 128x128 CTA, 256 threads, KC=64, 3-stage ------
#define TILE_STRIDE 72
#define HALF_BYTES 18432
#define BUF_BYTES 36864
#define SMEM_BYTES (3*BUF_BYTES)
#define STG_STRIDE 132

__device__ __forceinline__ void issue_tile(uint32_t dstBase,
                                           const __half* __restrict__ src,
                                           int row0, int kc, int tid) {
    #pragma unroll
    for (int i = 0; i < 4; i++) {
        int ci  = i * 256 + tid;
        int r   = ci >> 3;
        int c16 = ci & 7;
        uint32_t dst = dstBase + (uint32_t)(r * (TILE_STRIDE * 2) + c16 * 16);
        cp_async16(dst, src + (size_t)(row0 + r) * KP + kc + c16 * 8);
    }
}

__device__ __forceinline__ float expclip(float v) {
    return __expf(fminf(fmaxf(v, -1.f), 1.f));
}
__device__ __forceinline__ float tanh09(float v) {
    float xc = fminf(fmaxf(0.5f * v, -15.f), 15.f);
    float e = __expf(2.f * xc);
    return 0.9f * __fdividef(e - 1.f, e + 1.f);
}

__global__ void __launch_bounds__(256, 2) gemm_tc()
{
    extern __shared__ char smem[];
    uint32_t sbase = smem_u32(smem);
    int tid = threadIdx.x, wid = tid >> 5, lane = tid & 31;
    int m0 = blockIdx.x * 128;
    int n0 = blockIdx.y * 128;

    int wm = (wid & 3) * 32;
    int wn = (wid >> 2) * 64;
    int lr = lane & 15;
    int lc = (lane >> 4) * 8;

    float acc[2][8][4];
    #pragma unroll
    for (int mi = 0; mi < 2; mi++)
        #pragma unroll
        for (int ni = 0; ni < 8; ni++)
            #pragma unroll
            for (int q = 0; q < 4; q++) acc[mi][ni][q] = 0.f;

    issue_tile(sbase,              g_Ap, m0, 0, tid);
    issue_tile(sbase + HALF_BYTES, g_Bp, n0, 0, tid);
    CP_COMMIT();
    issue_tile(sbase + BUF_BYTES,              g_Ap, m0, KC, tid);
    issue_tile(sbase + BUF_BYTES + HALF_BYTES, g_Bp, n0, KC, tid);
    CP_COMMIT();

    for (int c = 0; c < NCH; c++) {
        if (c + 1 < NCH) { CP_WAIT(1); } else { CP_WAIT(0); }
        __syncthreads();
        if (c + 2 < NCH) {
            uint32_t nb = sbase + (uint32_t)(((c + 2) % 3) * BUF_BYTES);
            issue_tile(nb,              g_Ap, m0, (c + 2) * KC, tid);
            issue_tile(nb + HALF_BYTES, g_Bp, n0, (c + 2) * KC, tid);
            CP_COMMIT();
        }
        uint32_t aBase = sbase + (uint32_t)((c % 3) * BUF_BYTES);
        uint32_t bBase = aBase + HALF_BYTES;
        #pragma unroll
        for (int ks = 0; ks < 4; ks++) {
            uint32_t af[2][4];
            #pragma unroll
            for (int mi = 0; mi < 2; mi++)
                ldmx4(af[mi], aBase + (uint32_t)(((wm + mi * 16 + lr) * TILE_STRIDE
                                                  + ks * 16 + lc) * 2));
            uint32_t bf[4][4];
            #pragma unroll
            for (int nb = 0; nb < 4; nb++)
                ldmx4(bf[nb], bBase + (uint32_t)(((wn + nb * 16 + lr) * TILE_STRIDE
                                                  + ks * 16 + lc) * 2));
            #pragma unroll
            for (int mi = 0; mi < 2; mi++)
                #pragma unroll
                for (int nb = 0; nb < 4; nb++) {
                    mma16816(acc[mi][nb * 2 + 0], af[mi], bf[nb][0], bf[nb][2]);
                    mma16816(acc[mi][nb * 2 + 1], af[mi], bf[nb][1], bf[nb][3]);
                }
        }
    }
    __syncthreads();

    float* stage = (float*)smem;
    int gr = lane >> 2;
    int gc = (lane & 3) * 2;
    #pragma unroll
    for (int mi = 0; mi < 2; mi++)
        #pragma unroll
        for (int ni = 0; ni < 8; ni++) {
            int row = wm + mi * 16 + gr;
            int col = wn + ni * 8 + gc;
            *(float2*)&stage[row * STG_STRIDE + col] =
                make_float2(acc[mi][ni][0], acc[mi][ni][1]);
            *(float2*)&stage[(row + 8) * STG_STRIDE + col] =
                make_float2(acc[mi][ni][2], acc[mi][ni][3]);
        }
    __syncthreads();

    // mode: 1 = exp(clip) [s_var, d0, d1 planes], 2 = 0.9*tanh(0.5x) [sum plane]
    int mode = 0;
    if (n0 == PS_VAR || (n0 >= PT_D0 && n0 < PT_SUM) || n0 >= PT_D1) mode = 1;
    else if (n0 >= PT_SUM && n0 < PT_D1) mode = 2;

    for (int i = tid; i < 128 * 32; i += 256) {
        int row = i >> 5, q = i & 31;
        int col = q * 4;
        float4 b4 = *(const float4*)&g_bias[n0 + col];
        const float* s = &stage[row * STG_STRIDE + col];
        float4 v = make_float4(s[0] + b4.x, s[1] + b4.y, s[2] + b4.z, s[3] + b4.w);
        if (mode == 1) {
            v.x = expclip(v.x); v.y = expclip(v.y); v.z = expclip(v.z); v.w = expclip(v.w);
        } else if (mode == 2) {
            v.x = tanh09(v.x); v.y = tanh09(v.y); v.z = tanh09(v.z); v.w = tanh09(v.w);
        }
        __stcs((float4*)&g_C[(size_t)(m0 + row) * NTOT + n0 + col], v);
    }
}

// ---------------- scan ----------------
struct Step { float smu, svar, tw, m0, m1, d0, sv, d1; };

__device__ __forceinline__ Step load_step(int row, int chain, int j) {
    const float* base = g_C + (size_t)row * NTOT;
    Step s;
    // s-planes: heavily reused across chains -> keep caching
    s.smu  = __ldg(base + PS_MU  + j);
    s.svar = __ldg(base + PS_VAR + j);
    // t-planes: streamed once -> evict-first (tw already includes sw)
    s.tw   = __ldcs(base + PT_W   + chain);
    s.m0   = __ldcs(base + PT_MU0 + chain);
    s.m1   = __ldcs(base + PT_MU1 + chain);
    s.d0   = __ldcs(base + PT_D0  + chain);
    s.sv   = __ldcs(base + PT_SUM + chain);
    s.d1   = __ldcs(base + PT_D1  + chain);
    return s;
}

// generic merge (t=0 prologue only)
__device__ __forceinline__ void merge2x2(
    float tmu0, float tmu1, float tv00, float tv01, float tv11,
    float nmu, float nvar, bool child,
    float& zeta, float& mu_new, float& var_new)
{
    float det  = tv00 * tv11 - tv01 * tv01;
    float idet = __fdividef(1.f, det);
    float a  = tv11 * idet;
    float bo = -tv01 * idet;
    float dd = tv00 * idet;
    float e0 = a  * tmu0 + bo * tmu1;
    float e1 = bo * tmu0 + dd * tmu1;
    float quad1 = e0 * e0 * tv00 + 2.f * e0 * e1 * tv01 + e1 * e1 * tv11;
    float l2   = __fdividef(1.f, nvar);
    float eta2 = nmu * l2;
    float den, keep, es, la, iden;
    if (child) { den = dd + l2; iden = __fdividef(1.f, den); keep = e0; es = e1 + eta2; la = a  - bo * bo * iden; }
    else       { den = a  + l2; iden = __fdividef(1.f, den); keep = e1; es = e0 + eta2; la = dd - bo * bo * iden; }
    float eta = keep - bo * iden * es;
    var_new = __fdividef(1.f, la);
    mu_new  = var_new * eta;
    float logp = __logf(det * nvar * den * la);
    zeta = -0.5f * (LOG2PI + logp + quad1 + nmu * nmu * l2
                    - es * es * iden - eta * eta * var_new);
}

// one scan step (short-critical-path form; tw includes sw)
__device__ __forceinline__ float scan_step(const Step& cur, float& mu_p, float& var_p)
{
    // off-path precompute
    float w01  = cur.sv * sqrtf(cur.d0 * cur.d1);
    float det  = cur.d0 * cur.d1 - w01 * w01;
    float idet = __frcp_rn(det);
    float a  = cur.d1 * idet;
    float bo = -w01 * idet;
    float dd = cur.d0 * idet;
    float e0 = a  * cur.m0 + bo * cur.m1;
    float e1 = bo * cur.m0 + dd * cur.m1;
    float quad1 = e0 * e0 * cur.d0 + 2.f * e0 * e1 * w01 + e1 * e1 * cur.d1;
    float bo2 = bo * bo;

    // recurrence critical path
    float vsum = var_p + cur.svar;
    float lg   = __log2f(vsum);
    float logv = lg * LN2F;
    float inv  = __frcp_rn(vsum);
    float nvar = fmaf(lg, -0.5f * LN2F, vsum);
    float nmu  = (mu_p * cur.svar + cur.smu * var_p) * inv;
    float diff = mu_p - cur.smu;
    float scale_c = -0.5f * (LOG2PI + logv + diff * diff * inv);

    float h    = fmaf(a, nvar, 1.f);
    float bo2n = bo2 * nvar;
    float p    = fmaf(dd, h, -bo2n);
    float rp   = __frcp_rn(p);
    float esn  = fmaf(e0, nvar, nmu);
    float etah = fmaf(e1, h, -bo * esn);
    float var_n = h * rp;
    float mu_n  = etah * rp;

    // zeta (off-path)
    float invn = __frcp_rn(nvar);
    float invh = __frcp_rn(h);
    float logdp = __log2f(det * p) * LN2F;
    float zeta = -0.5f * (LOG2PI + logdp + quad1
                          + nmu * nmu * invn
                          - esn * esn * invn * invh
                          - etah * etah * invh * rp);

    mu_p = mu_n; var_p = var_n;
    return scale_c + zeta + cur.tw;
}

#define RING 6

// single-wave: ceil(41616/288)=145 CTAs x 288 threads
__global__ __launch_bounds__(288) void scan_kernel(float* __restrict__ out)
{
    int q = blockIdx.x * 288 + threadIdx.x;
    if (q >= NCHAINS) return;
    int b = q / LL2;
    int chain = q - b * LL2;
    int j = chain % LL1;
    int row0 = b * TT;

    Step buf[RING];
    Step s0 = load_step(row0, chain, j);
    #pragma unroll
    for (int k = 0; k < RING; k++)
        buf[k] = load_step(row0 + 1 + k, chain, j);

    // ---- t = 0 prologue ----
    float v01 = s0.sv * sqrtf(s0.d0 * s0.d1);
    float sc0, mu_c, var_c;
    merge2x2(s0.m0, s0.m1, s0.d0, v01, s0.d1, s0.smu, s0.svar, true, sc0, mu_c, var_c);

    Step s1 = buf[0];
    float u01 = s1.sv * sqrtf(s1.d0 * s1.d1);
    float sp0, mu_p, var_p;
    merge2x2(s1.m0, s1.m1, s1.d0, u01, s1.d1, mu_c, var_c, false, sp0, mu_p, var_p);

    __stcs(out + (size_t)row0 * LL2 + chain, sc0 + sp0 + s0.tw);

    // ---- t = 1..252 in 42 blocks of 6 (static ring slots) ----
    float* optr = out + (size_t)row0 * LL2 + chain;
    for (int blk = 0; blk < 42; blk++) {
        int tbase = blk * RING + 1;
        #pragma unroll
        for (int u = 0; u < RING; u++) {
            int t = tbase + u;
            Step cur = buf[u];
            if (t + RING < TT)
                buf[u] = load_step(row0 + t + RING, chain, j);
            float r = scan_step(cur, mu_p, var_p);
            __stcs(optr + (size_t)t * LL2, r);
        }
    }
    // ---- tail t = 253, 254, 255 ----
    #pragma unroll
    for (int u = 0; u < 3; u++) {
        int t = 253 + u;
        float r = scan_step(buf[u], mu_p, var_p);
        __stcs(optr + (size_t)t * LL2, r);
    }
}

// ---------------- launch ----------------
extern "C" void kernel_launch(void* const* d_in, const int* in_sizes, int n_in,
                              void* d_out, int out_size)
{
    const float* x      = (const float*)d_in[0];
    const float* Ws_w   = (const float*)d_in[1];
    const float* bs_w   = (const float*)d_in[2];
    const float* Ws_mu  = (const float*)d_in[3];
    const float* bs_mu  = (const float*)d_in[4];
    const float* Ws_var = (const float*)d_in[5];
    const float* bs_var = (const float*)d_in[6];
    const float* Wt_w   = (const float*)d_in[7];
    const float* bt_w   = (const float*)d_in[8];
    const float* Wt_mu  = (const float*)d_in[9];
    const float* bt_mu  = (const float*)d_in[10];
    const float* Wt_var = (const float*)d_in[11];
    const float* bt_var = (const float*)d_in[12];
    float* out = (float*)d_out;

    cudaFuncSetAttribute(gemm_tc, cudaFuncAttributeMaxDynamicSharedMemorySize, SMEM_BYTES);

    prep_all<<<dim3(84, 16, 9), dim3(32, 8)>>>(x, Ws_w, Ws_mu, Ws_var, Wt_w, Wt_mu, Wt_var,
                                               bs_w, bs_mu, bs_var, bt_w, bt_mu, bt_var);

    gemm_tc<<<dim3(32, NTILES), 256, SMEM_BYTES>>>();

    scan_kernel<<<(NCHAINS + 287) / 288, 288>>>(out);
}

// round 14
// speedup vs baseline: 1.2842x; 1.0186x over previous
#include <cuda_runtime.h>
#include <cuda_fp16.h>
#include <math.h>
#include <stdint.h>

// ---------------- problem constants ----------------
#define BB 16
#define TT 256
#define DD 512
#define LL1 51
#define MM (BB*TT)            // 4096
#define LL2 (LL1*LL1)         // 2601
#define NCHAINS (BB*LL2)      // 41616
#define KP 512                // plain fp16 GEMM
#define KC 64
#define NCH (KP/KC)           // 8
#define LOG2PI 1.8378770664093453f
#define LN2F 0.6931471805599453f

// planar output layout (offsets multiples of 128)
#define NP_CH  2688
#define PS_W   0
#define PS_MU  128
#define PS_VAR 256
#define PT_W   384
#define PT_MU0 (PT_W  + NP_CH)   // 3072
#define PT_MU1 (PT_MU0 + NP_CH)  // 5760
#define PT_D0  (PT_MU1 + NP_CH)  // 8448
#define PT_SUM (PT_D0 + NP_CH)   // 11136
#define PT_D1  (PT_SUM + NP_CH)  // 13824
#define NTOT   (PT_D1 + NP_CH)   // 16512
#define NTILES 129               // 128-wide tiles

// ---------------- scratch (device globals) ----------------
__device__ __align__(256) __half g_Ap[(size_t)MM*KP];
__device__ __align__(256) __half g_Bp[(size_t)NTOT*KP];
__device__ __align__(256) float g_bias[NTOT];
__device__ __align__(256) float g_C[(size_t)MM*NTOT];

// ---------------- PTX helpers ----------------
__device__ __forceinline__ uint32_t smem_u32(const void* p) {
    uint32_t a;
    asm("{ .reg .u64 t; cvta.to.shared.u64 t, %1; cvt.u32.u64 %0, t; }" : "=r"(a) : "l"(p));
    return a;
}
__device__ __forceinline__ void cp_async16(uint32_t dst, const void* src) {
    asm volatile("cp.async.cg.shared.global [%0], [%1], 16;" :: "r"(dst), "l"(src));
}
#define CP_COMMIT() asm volatile("cp.async.commit_group;" ::: "memory")
#define CP_WAIT(n)  asm volatile("cp.async.wait_group %0;" :: "n"(n) : "memory")

__device__ __forceinline__ void ldmx4(uint32_t* r, uint32_t addr) {
    asm volatile("ldmatrix.sync.aligned.m8n8.x4.shared.b16 {%0,%1,%2,%3}, [%4];"
        : "=r"(r[0]), "=r"(r[1]), "=r"(r[2]), "=r"(r[3]) : "r"(addr));
}
__device__ __forceinline__ void mma16816(float* c, const uint32_t* a, uint32_t b0, uint32_t b1) {
    asm volatile("mma.sync.aligned.m16n8k16.row.col.f32.f16.f16.f32 "
        "{%0,%1,%2,%3}, {%4,%5,%6,%7}, {%8,%9}, {%0,%1,%2,%3};"
        : "+f"(c[0]), "+f"(c[1]), "+f"(c[2]), "+f"(c[3])
        : "r"(a[0]), "r"(a[1]), "r"(a[2]), "r"(a[3]), "r"(b0), "r"(b1));
}

// ---------------- fused prep: 8 W jobs + x-convert + bias ----------------
// z: 0 = tw (+ s_w fold), 1 = s_mu, 2 = s_var, 3 = mu0, 4 = mu1,
//    5 = d0, 6 = sum, 7 = d1, 8 = x + bias
__global__ void prep_all(const float* __restrict__ x,
    const float* __restrict__ Ws_w, const float* __restrict__ Ws_mu, const float* __restrict__ Ws_var,
    const float* __restrict__ Wt_w, const float* __restrict__ Wt_mu, const float* __restrict__ Wt_var,
    const float* __restrict__ bsw, const float* __restrict__ bsmu, const float* __restrict__ bsvar,
    const float* __restrict__ btw, const float* __restrict__ btmu, const float* __restrict__ btvar)
{
    int z = blockIdx.z;
    int tx = threadIdx.x, ty = threadIdx.y;
    int tid = ty * 32 + tx;

    if (z == 8) {
        int linb = blockIdx.y * gridDim.x + blockIdx.x;
        int nth  = gridDim.x * gridDim.y * 256;
        int gtid = linb * 256 + tid;
        for (int t = gtid; t < MM * DD; t += nth)
            g_Ap[t] = __float2half(x[t]);
        for (int c = gtid; c < NTOT; c += nth) {
            float v = 0.f;
            if (c < PS_MU)        { /* s_w plane unused */ }
            else if (c < PS_VAR)  { int n = c - PS_MU;  if (n < LL1) v = bsmu[n]; }
            else if (c < PT_W)    { int n = c - PS_VAR; if (n < LL1) v = bsvar[n]; }
            else if (c < PT_MU0)  { int n = c - PT_W;   if (n < LL2) v = btw[n] + bsw[n % LL1]; }
            else if (c < PT_MU1)  { int n = c - PT_MU0; if (n < LL2) v = btmu[2 * n]; }
            else if (c < PT_D0)   { int n = c - PT_MU1; if (n < LL2) v = btmu[2 * n + 1]; }
            else if (c < PT_SUM)  { int n = c - PT_D0;  if (n < LL2) v = btvar[4 * n]; }
            else if (c < PT_D1)   { int n = c - PT_SUM; if (n < LL2) v = btvar[4 * n + 1] + btvar[4 * n + 2]; }
            else                  { int n = c - PT_D1;  if (n < LL2) v = btvar[4 * n + 3]; }
            g_bias[c] = v;
        }
        return;
    }

    int dstOff, nValid, bx;
    switch (z) {
        case 0: dstOff = PT_W;   nValid = LL2; bx = 84; break;
        case 1: dstOff = PS_MU;  nValid = LL1; bx = 4;  break;
        case 2: dstOff = PS_VAR; nValid = LL1; bx = 4;  break;
        case 3: dstOff = PT_MU0; nValid = LL2; bx = 84; break;
        case 4: dstOff = PT_MU1; nValid = LL2; bx = 84; break;
        case 5: dstOff = PT_D0;  nValid = LL2; bx = 84; break;
        case 6: dstOff = PT_SUM; nValid = LL2; bx = 84; break;
        default:dstOff = PT_D1;  nValid = LL2; bx = 84; break;
    }
    if ((int)blockIdx.x >= bx) return;

    __shared__ float tile[32][33];
    int n = blockIdx.x * 32 + tx;
    #pragma unroll
    for (int i = 0; i < 4; i++) {
        int k = blockIdx.y * 32 + ty + i * 8;
        float v = 0.f;
        if (n < nValid) {
            switch (z) {
                case 0: v = Wt_w[(size_t)k * LL2 + n] + Ws_w[(size_t)k * LL1 + n % LL1]; break;
                case 1: v = Ws_mu[(size_t)k * LL1 + n]; break;
                case 2: v = Ws_var[(size_t)k * LL1 + n]; break;
                case 3: v = Wt_mu[(size_t)k * (LL2 * 2) + 2 * n]; break;
                case 4: v = Wt_mu[(size_t)k * (LL2 * 2) + 2 * n + 1]; break;
                case 5: v = Wt_var[(size_t)k * (LL2 * 4) + 4 * n]; break;
                case 6: v = Wt_var[(size_t)k * (LL2 * 4) + 4 * n + 1]
                          + Wt_var[(size_t)k * (LL2 * 4) + 4 * n + 2]; break;
                default:v = Wt_var[(size_t)k * (LL2 * 4) + 4 * n + 3]; break;
            }
        }
        tile[ty + i * 8][tx] = v;
    }
    __syncthreads();
    #pragma unroll
    for (int i = 0; i < 4; i++) {
        int n2 = blockIdx.x * 32 + ty + i * 8;
        int k2 = blockIdx.y * 32 + tx;
        g_Bp[(size_t)(dstOff + n2) * KP + k2] = __float2half(tile[tx][ty + i * 8]);
    }
}

// ---------------- HMMA GEMM: 128x128 CTA, 256 threads, KC=64, 3-stage ------
#define TILE_STRIDE 72
#define HALF_BYTES 18432
#define BUF_BYTES 36864
#define SMEM_BYTES (3*BUF_BYTES)
#define STG_STRIDE 132

__device__ __forceinline__ void issue_tile(uint32_t dstBase,
                                           const __half* __restrict__ src,
                                           int row0, int kc, int tid) {
    #pragma unroll
    for (int i = 0; i < 4; i++) {
        int ci  = i * 256 + tid;
        int r   = ci >> 3;
        int c16 = ci & 7;
        uint32_t dst = dstBase + (uint32_t)(r * (TILE_STRIDE * 2) + c16 * 16);
        cp_async16(dst, src + (size_t)(row0 + r) * KP + kc + c16 * 8);
    }
}

__device__ __forceinline__ float expclip(float v) {
    return __expf(fminf(fmaxf(v, -1.f), 1.f));
}
__device__ __forceinline__ float tanh09(float v) {
    float xc = fminf(fmaxf(0.5f * v, -15.f), 15.f);
    float e = __expf(2.f * xc);
    return 0.9f * __fdividef(e - 1.f, e + 1.f);
}

__global__ void __launch_bounds__(256, 2) gemm_tc()
{
    extern __shared__ char smem[];
    uint32_t sbase = smem_u32(smem);
    int tid = threadIdx.x, wid = tid >> 5, lane = tid & 31;
    int m0 = blockIdx.x * 128;
    int n0 = blockIdx.y * 128;

    int wm = (wid & 3) * 32;
    int wn = (wid >> 2) * 64;
    int lr = lane & 15;
    int lc = (lane >> 4) * 8;

    float acc[2][8][4];
    #pragma unroll
    for (int mi = 0; mi < 2; mi++)
        #pragma unroll
        for (int ni = 0; ni < 8; ni++)
            #pragma unroll
            for (int q = 0; q < 4; q++) acc[mi][ni][q] = 0.f;

    issue_tile(sbase,              g_Ap, m0, 0, tid);
    issue_tile(sbase + HALF_BYTES, g_Bp, n0, 0, tid);
    CP_COMMIT();
    issue_tile(sbase + BUF_BYTES,              g_Ap, m0, KC, tid);
    issue_tile(sbase + BUF_BYTES + HALF_BYTES, g_Bp, n0, KC, tid);
    CP_COMMIT();

    for (int c = 0; c < NCH; c++) {
        if (c + 1 < NCH) { CP_WAIT(1); } else { CP_WAIT(0); }
        __syncthreads();
        if (c + 2 < NCH) {
            uint32_t nb = sbase + (uint32_t)(((c + 2) % 3) * BUF_BYTES);
            issue_tile(nb,              g_Ap, m0, (c + 2) * KC, tid);
            issue_tile(nb + HALF_BYTES, g_Bp, n0, (c + 2) * KC, tid);
            CP_COMMIT();
        }
        uint32_t aBase = sbase + (uint32_t)((c % 3) * BUF_BYTES);
        uint32_t bBase = aBase + HALF_BYTES;
        #pragma unroll
        for (int ks = 0; ks < 4; ks++) {
            uint32_t af[2][4];
            #pragma unroll
            for (int mi = 0; mi < 2; mi++)
                ldmx4(af[mi], aBase + (uint32_t)(((wm + mi * 16 + lr) * TILE_STRIDE
                                                  + ks * 16 + lc) * 2));
            uint32_t bf[4][4];
            #pragma unroll
            for (int nb = 0; nb < 4; nb++)
                ldmx4(bf[nb], bBase + (uint32_t)(((wn + nb * 16 + lr) * TILE_STRIDE
                                                  + ks * 16 + lc) * 2));
            #pragma unroll
            for (int mi = 0; mi < 2; mi++)
                #pragma unroll
                for (int nb = 0; nb < 4; nb++) {
                    mma16816(acc[mi][nb * 2 + 0], af[mi], bf[nb][0], bf[nb][2]);
                    mma16816(acc[mi][nb * 2 + 1], af[mi], bf[nb][1], bf[nb][3]);
                }
        }
    }
    __syncthreads();

    float* stage = (float*)smem;
    int gr = lane >> 2;
    int gc = (lane & 3) * 2;
    #pragma unroll
    for (int mi = 0; mi < 2; mi++)
        #pragma unroll
        for (int ni = 0; ni < 8; ni++) {
            int row = wm + mi * 16 + gr;
            int col = wn + ni * 8 + gc;
            *(float2*)&stage[row * STG_STRIDE + col] =
                make_float2(acc[mi][ni][0], acc[mi][ni][1]);
            *(float2*)&stage[(row + 8) * STG_STRIDE + col] =
                make_float2(acc[mi][ni][2], acc[mi][ni][3]);
        }
    __syncthreads();

    // mode: 1 = exp(clip) [s_var, d0, d1 planes], 2 = 0.9*tanh(0.5x) [sum plane]
    int mode = 0;
    if (n0 == PS_VAR || (n0 >= PT_D0 && n0 < PT_SUM) || n0 >= PT_D1) mode = 1;
    else if (n0 >= PT_SUM && n0 < PT_D1) mode = 2;

    for (int i = tid; i < 128 * 32; i += 256) {
        int row = i >> 5, q = i & 31;
        int col = q * 4;
        float4 b4 = *(const float4*)&g_bias[n0 + col];
        const float* s = &stage[row * STG_STRIDE + col];
        float4 v = make_float4(s[0] + b4.x, s[1] + b4.y, s[2] + b4.z, s[3] + b4.w);
        if (mode == 1) {
            v.x = expclip(v.x); v.y = expclip(v.y); v.z = expclip(v.z); v.w = expclip(v.w);
        } else if (mode == 2) {
            v.x = tanh09(v.x); v.y = tanh09(v.y); v.z = tanh09(v.z); v.w = tanh09(v.w);
        }
        *(float4*)&g_C[(size_t)(m0 + row) * NTOT + n0 + col] = v;   // cached store
    }
}

// ---------------- scan ----------------
struct Step { float smu, svar, tw, m0, m1, d0, sv, d1; };

__device__ __forceinline__ Step load_step(int row, int chain, int j) {
    const float* base = g_C + (size_t)row * NTOT;
    Step s;
    // s-planes: heavily reused across chains -> keep caching
    s.smu  = __ldg(base + PS_MU  + j);
    s.svar = __ldg(base + PS_VAR + j);
    // t-planes: streamed once -> evict-first (tw already includes sw)
    s.tw   = __ldcs(base + PT_W   + chain);
    s.m0   = __ldcs(base + PT_MU0 + chain);
    s.m1   = __ldcs(base + PT_MU1 + chain);
    s.d0   = __ldcs(base + PT_D0  + chain);
    s.sv   = __ldcs(base + PT_SUM + chain);
    s.d1   = __ldcs(base + PT_D1  + chain);
    return s;
}

// generic merge (t=0 prologue only)
__device__ __forceinline__ void merge2x2(
    float tmu0, float tmu1, float tv00, float tv01, float tv11,
    float nmu, float nvar, bool child,
    float& zeta, float& mu_new, float& var_new)
{
    float det  = tv00 * tv11 - tv01 * tv01;
    float idet = __fdividef(1.f, det);
    float a  = tv11 * idet;
    float bo = -tv01 * idet;
    float dd = tv00 * idet;
    float e0 = a  * tmu0 + bo * tmu1;
    float e1 = bo * tmu0 + dd * tmu1;
    float quad1 = e0 * e0 * tv00 + 2.f * e0 * e1 * tv01 + e1 * e1 * tv11;
    float l2   = __fdividef(1.f, nvar);
    float eta2 = nmu * l2;
    float den, keep, es, la, iden;
    if (child) { den = dd + l2; iden = __fdividef(1.f, den); keep = e0; es = e1 + eta2; la = a  - bo * bo * iden; }
    else       { den = a  + l2; iden = __fdividef(1.f, den); keep = e1; es = e0 + eta2; la = dd - bo * bo * iden; }
    float eta = keep - bo * iden * es;
    var_new = __fdividef(1.f, la);
    mu_new  = var_new * eta;
    float logp = __logf(det * nvar * den * la);
    zeta = -0.5f * (LOG2PI + logp + quad1 + nmu * nmu * l2
                    - es * es * iden - eta * eta * var_new);
}

// one scan step (short-critical-path form; tw includes sw)
__device__ __forceinline__ float scan_step(const Step& cur, float& mu_p, float& var_p)
{
    // off-path precompute
    float w01  = cur.sv * sqrtf(cur.d0 * cur.d1);
    float det  = cur.d0 * cur.d1 - w01 * w01;
    float idet = __frcp_rn(det);
    float a  = cur.d1 * idet;
    float bo = -w01 * idet;
    float dd = cur.d0 * idet;
    float e0 = a  * cur.m0 + bo * cur.m1;
    float e1 = bo * cur.m0 + dd * cur.m1;
    float quad1 = e0 * e0 * cur.d0 + 2.f * e0 * e1 * w01 + e1 * e1 * cur.d1;
    float bo2 = bo * bo;

    // recurrence critical path
    float vsum = var_p + cur.svar;
    float lg   = __log2f(vsum);
    float logv = lg * LN2F;
    float inv  = __frcp_rn(vsum);
    float nvar = fmaf(lg, -0.5f * LN2F, vsum);
    float nmu  = (mu_p * cur.svar + cur.smu * var_p) * inv;
    float diff = mu_p - cur.smu;
    float scale_c = -0.5f * (LOG2PI + logv + diff * diff * inv);

    float h    = fmaf(a, nvar, 1.f);
    float bo2n = bo2 * nvar;
    float p    = fmaf(dd, h, -bo2n);
    float rp   = __frcp_rn(p);
    float esn  = fmaf(e0, nvar, nmu);
    float etah = fmaf(e1, h, -bo * esn);
    float var_n = h * rp;
    float mu_n  = etah * rp;

    // zeta (off-path)
    float invn = __frcp_rn(nvar);
    float invh = __frcp_rn(h);
    float logdp = __log2f(det * p) * LN2F;
    float zeta = -0.5f * (LOG2PI + logdp + quad1
                          + nmu * nmu * invn
                          - esn * esn * invn * invh
                          - etah * etah * invh * rp);

    mu_p = mu_n; var_p = var_n;
    return scale_c + zeta + cur.tw;
}

#define RING 6

// single-wave: ceil(41616/288)=145 CTAs x 288 threads
__global__ __launch_bounds__(288) void scan_kernel(float* __restrict__ out)
{
    int q = blockIdx.x * 288 + threadIdx.x;
    if (q >= NCHAINS) return;
    int b = q / LL2;
    int chain = q - b * LL2;
    int j = chain % LL1;
    int row0 = b * TT;

    Step buf[RING];
    Step s0 = load_step(row0, chain, j);
    #pragma unroll
    for (int k = 0; k < RING; k++)
        buf[k] = load_step(row0 + 1 + k, chain, j);

    // ---- t = 0 prologue ----
    float v01 = s0.sv * sqrtf(s0.d0 * s0.d1);
    float sc0, mu_c, var_c;
    merge2x2(s0.m0, s0.m1, s0.d0, v01, s0.d1, s0.smu, s0.svar, true, sc0, mu_c, var_c);

    Step s1 = buf[0];
    float u01 = s1.sv * sqrtf(s1.d0 * s1.d1);
    float sp0, mu_p, var_p;
    merge2x2(s1.m0, s1.m1, s1.d0, u01, s1.d1, mu_c, var_c, false, sp0, mu_p, var_p);

    __stcs(out + (size_t)row0 * LL2 + chain, sc0 + sp0 + s0.tw);

    // ---- t = 1..252 in 42 blocks of 6 (static ring slots) ----
    float* optr = out + (size_t)row0 * LL2 + chain;
    for (int blk = 0; blk < 42; blk++) {
        int tbase = blk * RING + 1;
        #pragma unroll
        for (int u = 0; u < RING; u++) {
            int t = tbase + u;
            Step cur = buf[u];
            if (t + RING < TT)
                buf[u] = load_step(row0 + t + RING, chain, j);
            float r = scan_step(cur, mu_p, var_p);
            __stcs(optr + (size_t)t * LL2, r);
        }
    }
    // ---- tail t = 253, 254, 255 ----
    #pragma unroll
    for (int u = 0; u < 3; u++) {
        int t = 253 + u;
        float r = scan_step(buf[u], mu_p, var_p);
        __stcs(optr + (size_t)t * LL2, r);
    }
}

// ---------------- launch ----------------
extern "C" void kernel_launch(void* const* d_in, const int* in_sizes, int n_in,
                              void* d_out, int out_size)
{
    const float* x      = (const float*)d_in[0];
    const float* Ws_w   = (const float*)d_in[1];
    const float* bs_w   = (const float*)d_in[2];
    const float* Ws_mu  = (const float*)d_in[3];
    const float* bs_mu  = (const float*)d_in[4];
    const float* Ws_var = (const float*)d_in[5];
    const float* bs_var = (const float*)d_in[6];
    const float* Wt_w   = (const float*)d_in[7];
    const float* bt_w   = (const float*)d_in[8];
    const float* Wt_mu  = (const float*)d_in[9];
    const float* bt_mu  = (const float*)d_in[10];
    const float* Wt_var = (const float*)d_in[11];
    const float* bt_var = (const float*)d_in[12];
    float* out = (float*)d_out;

    cudaFuncSetAttribute(gemm_tc, cudaFuncAttributeMaxDynamicSharedMemorySize, SMEM_BYTES);

    prep_all<<<dim3(84, 16, 9), dim3(32, 8)>>>(x, Ws_w, Ws_mu, Ws_var, Wt_w, Wt_mu, Wt_var,
                                               bs_w, bs_mu, bs_var, bt_w, bt_mu, bt_var);

    gemm_tc<<<dim3(32, NTILES), 256, SMEM_BYTES>>>();

    scan_kernel<<<(NCHAINS + 287) / 288, 288>>>(out);
}